// round 6
// baseline (speedup 1.0000x reference)
#include <cuda_runtime.h>
#include <cstdint>

// GRU_12962211299468 : B=65536, T=9, I=57, H=2, O=1, fp32
// Round 6: round-2 compute path (smem weights, broadcast LDS; scalar x LDS,
// stride 57 conflict-free) in the round-4 occupancy shape:
//   NB=8 batch/block, 96 threads, 18.5 KB smem, launch_bounds(96,12)
//   -> up to 12 CTAs/SM (~36 warps). Cross-CTA phase interleaving hides DRAM
//   latency without explicit pipelining (rounds 3/5 showed pipelines lose).

#define T_STEPS 9
#define I_DIM   57
#define NB      8
#define ROWS    (NB * T_STEPS)          // 72
#define NTHR    96                      // 3 warps
#define XFLT    (ROWS * I_DIM)          // 4104 floats (16416 B, contiguous)
#define XV4     (XFLT / 4)              // 1026
#define GRID    (65536 / NB)            // 8192
#define WROW    60                      // padded W_ih row stride (16B aligned)

__device__ __forceinline__ float sigf(float v) {
    return 1.0f / (1.0f + __expf(-v));
}
__device__ __forceinline__ float tanh_ex(float v) {
    return 1.0f - 2.0f / (__expf(2.0f * v) + 1.0f);
}

__global__ __launch_bounds__(NTHR, 12) void gru_r6(
    const float* __restrict__ x,
    const float* __restrict__ Wih,   // [6,57]
    const float* __restrict__ Whh,   // [6,2]
    const float* __restrict__ bih,   // [6]
    const float* __restrict__ bhh,   // [6]
    const float* __restrict__ fcw,   // [2]
    const float* __restrict__ fcb,   // [1]
    float* __restrict__ out)         // [B]
{
    __shared__ __align__(16) float sx[XFLT];   // 16416 B
    __shared__ float sw[6 * WROW];             //  1440 B
    __shared__ float sgx[ROWS * 6];            //  1728 B

    const int tid = threadIdx.x;
    const int b0  = blockIdx.x * NB;

    // ---- stage W_ih into padded smem rows (single pass, no WAW) ----
    for (int j = tid; j < 6 * WROW; j += NTHR) {
        int g = j / WROW;
        int i = j - g * WROW;
        sw[j] = (i < I_DIM) ? Wih[g * I_DIM + i] : 0.0f;
    }

    // ---- stage x tile: contiguous, vectorized, coalesced, high MLP ----
    {
        const float4* gsrc = reinterpret_cast<const float4*>(x) +
                             (size_t)blockIdx.x * XV4;
        float4* sdst = reinterpret_cast<float4*>(sx);
#pragma unroll 11
        for (int j = tid; j < XV4; j += NTHR)
            sdst[j] = __ldg(gsrc + j);
    }
    __syncthreads();

    // ---- projection: one (b,t) row per thread (tid < 72) ----
    if (tid < ROWS) {
        const float* row = &sx[tid * I_DIM];   // stride 57 (odd): conflict-free

        float g0 = bih[0], g1 = bih[1], g2 = bih[2];
        float g3 = bih[3], g4 = bih[4], g5 = bih[5];

#pragma unroll
        for (int c = 0; c < 14; ++c) {
            float x0 = row[4 * c + 0];
            float x1 = row[4 * c + 1];
            float x2 = row[4 * c + 2];
            float x3 = row[4 * c + 3];
            float4 v;
            v = *reinterpret_cast<const float4*>(&sw[0 * WROW + 4 * c]);
            g0 += v.x * x0 + v.y * x1 + v.z * x2 + v.w * x3;
            v = *reinterpret_cast<const float4*>(&sw[1 * WROW + 4 * c]);
            g1 += v.x * x0 + v.y * x1 + v.z * x2 + v.w * x3;
            v = *reinterpret_cast<const float4*>(&sw[2 * WROW + 4 * c]);
            g2 += v.x * x0 + v.y * x1 + v.z * x2 + v.w * x3;
            v = *reinterpret_cast<const float4*>(&sw[3 * WROW + 4 * c]);
            g3 += v.x * x0 + v.y * x1 + v.z * x2 + v.w * x3;
            v = *reinterpret_cast<const float4*>(&sw[4 * WROW + 4 * c]);
            g4 += v.x * x0 + v.y * x1 + v.z * x2 + v.w * x3;
            v = *reinterpret_cast<const float4*>(&sw[5 * WROW + 4 * c]);
            g5 += v.x * x0 + v.y * x1 + v.z * x2 + v.w * x3;
        }
        {
            float xs = row[56];
            g0 += sw[0 * WROW + 56] * xs;
            g1 += sw[1 * WROW + 56] * xs;
            g2 += sw[2 * WROW + 56] * xs;
            g3 += sw[3 * WROW + 56] * xs;
            g4 += sw[4 * WROW + 56] * xs;
            g5 += sw[5 * WROW + 56] * xs;
        }

        float* gq = &sgx[tid * 6];
        gq[0] = g0; gq[1] = g1; gq[2] = g2;
        gq[3] = g3; gq[4] = g4; gq[5] = g5;
    }
    __syncthreads();

    // ---- recurrence + FC: lanes 24-31 of warp 2 ----
    if (tid >= 88) {
        const int j = tid - 88;
        const float w00 = Whh[0],  w01 = Whh[1];
        const float w10 = Whh[2],  w11 = Whh[3];
        const float w20 = Whh[4],  w21 = Whh[5];
        const float w30 = Whh[6],  w31 = Whh[7];
        const float w40 = Whh[8],  w41 = Whh[9];
        const float w50 = Whh[10], w51 = Whh[11];
        const float bh0 = bhh[0], bh1 = bhh[1], bh2 = bhh[2];
        const float bh3 = bhh[3], bh4 = bhh[4], bh5 = bhh[5];

        const float* gp = &sgx[j * (T_STEPS * 6)];  // stride 54: conflict-free
        float h0 = 0.0f, h1 = 0.0f;

#pragma unroll
        for (int t = 0; t < T_STEPS; ++t) {
            float q0 = gp[6 * t + 0];
            float q1 = gp[6 * t + 1];
            float q2 = gp[6 * t + 2];
            float q3 = gp[6 * t + 3];
            float q4 = gp[6 * t + 4];
            float q5 = gp[6 * t + 5];

            float a0 = w00 * h0 + w01 * h1 + bh0;
            float a1 = w10 * h0 + w11 * h1 + bh1;
            float a2 = w20 * h0 + w21 * h1 + bh2;
            float a3 = w30 * h0 + w31 * h1 + bh3;
            float a4 = w40 * h0 + w41 * h1 + bh4;
            float a5 = w50 * h0 + w51 * h1 + bh5;

            float r0 = sigf(q0 + a0);
            float r1 = sigf(q1 + a1);
            float z0 = sigf(q2 + a2);
            float z1 = sigf(q3 + a3);
            float n0 = tanh_ex(q4 + r0 * a4);
            float n1 = tanh_ex(q5 + r1 * a5);

            h0 = (1.0f - z0) * n0 + z0 * h0;
            h1 = (1.0f - z1) * n1 + z1 * h1;
        }

        out[b0 + j] = fcw[0] * h0 + fcw[1] * h1 + fcb[0];
    }
}

extern "C" void kernel_launch(void* const* d_in, const int* in_sizes, int n_in,
                              void* d_out, int out_size) {
    const float* x   = (const float*)d_in[0];
    const float* Wih = (const float*)d_in[1];
    const float* Whh = (const float*)d_in[2];
    const float* bih = (const float*)d_in[3];
    const float* bhh = (const float*)d_in[4];
    const float* fcw = (const float*)d_in[5];
    const float* fcb = (const float*)d_in[6];
    float* out = (float*)d_out;

    (void)in_sizes; (void)n_in; (void)out_size;

    gru_r6<<<GRID, NTHR>>>(x, Wih, Whh, bih, bhh, fcw, fcb, out);
}

// round 8
// speedup vs baseline: 1.6000x; 1.6000x over previous
#include <cuda_runtime.h>
#include <cstdint>

// GRU_12962211299468 : B=65536, T=9, I=57, H=2, O=1, fp32
// Round 8: round-7 two-kernel split with the scatter-index bug fixed
// (b = r/9 via proper wide magic-multiply emitted by ptxas; round 7 used a
//  hand-rolled 32-bit multiply whose high word was discarded -> garbage b).
//  K1: warp-private tiles, zero block barriers in the hot path.
//  K2: thread = batch element, register-only recurrence.

#define T_STEPS 9
#define I_DIM   57
#define B_TOT   65536
#define NROWS_T (B_TOT * T_STEPS)       // 589824 rows total
#define RPW     32                      // rows per warp
#define RPW_FLT (RPW * I_DIM)           // 1824 floats per warp tile
#define RPW_V4  (RPW_FLT / 4)           // 456 float4
#define WARPS_K1 (NROWS_T / RPW)        // 18432 warps
#define CWARPS  4                       // warps per CTA in K1
#define K1_THR  (CWARPS * 32)           // 128
#define K1_GRID (WARPS_K1 / CWARPS)     // 4608
#define WROW    60                      // padded W_ih row stride
#define GXPAD   56                      // padded floats per batch elem (16B mult)

__device__ __align__(16) float g_gx[(size_t)B_TOT * GXPAD];   // 14.7 MB scratch

__device__ __forceinline__ float sigf(float v) {
    return 1.0f / (1.0f + __expf(-v));
}
__device__ __forceinline__ float tanh_ex(float v) {
    return 1.0f - 2.0f / (__expf(2.0f * v) + 1.0f);
}

// ---------------------------------------------------------------- K1 ----
__global__ __launch_bounds__(K1_THR, 7) void gru_proj(
    const float* __restrict__ x,
    const float* __restrict__ Wih,   // [6,57]
    const float* __restrict__ bih)   // [6]
{
    __shared__ __align__(16) float sx[CWARPS][RPW_FLT];  // 4 x 7296 B
    __shared__ float sw[6 * WROW];                       // 1440 B

    const int tid  = threadIdx.x;
    const int wid  = tid >> 5;
    const int lane = tid & 31;

    // one-time weight staging (single barrier, outside the hot path)
    for (int j = tid; j < 6 * WROW; j += K1_THR) {
        int g = j / WROW;
        int i = j - g * WROW;
        sw[j] = (i < I_DIM) ? Wih[g * I_DIM + i] : 0.0f;
    }
    __syncthreads();

    const float bi0 = bih[0], bi1 = bih[1], bi2 = bih[2];
    const float bi3 = bih[3], bi4 = bih[4], bi5 = bih[5];

    const int wg = blockIdx.x * CWARPS + wid;      // global warp id, < 18432

    // ---- stage this warp's 1824 contiguous floats (coalesced, high MLP) ----
    {
        const float4* src = reinterpret_cast<const float4*>(x) + (size_t)wg * RPW_V4;
        float4* dst = reinterpret_cast<float4*>(sx[wid]);
#pragma unroll
        for (int k = 0; k < 15; ++k) {
            int j = lane + 32 * k;
            if (j < RPW_V4) dst[j] = __ldg(src + j);
        }
    }
    __syncwarp();

    // ---- lane = one row: 6 x 57 dot products ----
    const float* row = &sx[wid][lane * I_DIM];     // stride 57 (odd): conflict-free

    float g0 = bi0, g1 = bi1, g2 = bi2, g3 = bi3, g4 = bi4, g5 = bi5;
#pragma unroll
    for (int c = 0; c < 14; ++c) {
        float x0 = row[4 * c + 0];
        float x1 = row[4 * c + 1];
        float x2 = row[4 * c + 2];
        float x3 = row[4 * c + 3];
        float4 v;
        v = *reinterpret_cast<const float4*>(&sw[0 * WROW + 4 * c]);
        g0 += v.x * x0 + v.y * x1 + v.z * x2 + v.w * x3;
        v = *reinterpret_cast<const float4*>(&sw[1 * WROW + 4 * c]);
        g1 += v.x * x0 + v.y * x1 + v.z * x2 + v.w * x3;
        v = *reinterpret_cast<const float4*>(&sw[2 * WROW + 4 * c]);
        g2 += v.x * x0 + v.y * x1 + v.z * x2 + v.w * x3;
        v = *reinterpret_cast<const float4*>(&sw[3 * WROW + 4 * c]);
        g3 += v.x * x0 + v.y * x1 + v.z * x2 + v.w * x3;
        v = *reinterpret_cast<const float4*>(&sw[4 * WROW + 4 * c]);
        g4 += v.x * x0 + v.y * x1 + v.z * x2 + v.w * x3;
        v = *reinterpret_cast<const float4*>(&sw[5 * WROW + 4 * c]);
        g5 += v.x * x0 + v.y * x1 + v.z * x2 + v.w * x3;
    }
    {
        float xs = row[56];
        g0 += sw[0 * WROW + 56] * xs;
        g1 += sw[1 * WROW + 56] * xs;
        g2 += sw[2 * WROW + 56] * xs;
        g3 += sw[3 * WROW + 56] * xs;
        g4 += sw[4 * WROW + 56] * xs;
        g5 += sw[5 * WROW + 56] * xs;
    }

    // ---- write 6 gates to padded gx[b][t] ----
    const int r = wg * RPW + lane;                 // global row = 9b + t
    const int b = r / 9;                           // ptxas emits wide magic-mul
    const int t = r - 9 * b;
    float* o = &g_gx[(size_t)b * GXPAD + 6 * t];   // byte addr 8-aligned
    reinterpret_cast<float2*>(o)[0] = make_float2(g0, g1);
    reinterpret_cast<float2*>(o)[1] = make_float2(g2, g3);
    reinterpret_cast<float2*>(o)[2] = make_float2(g4, g5);
}

// ---------------------------------------------------------------- K2 ----
__global__ __launch_bounds__(128) void gru_recur(
    const float* __restrict__ Whh,   // [6,2]
    const float* __restrict__ bhh,   // [6]
    const float* __restrict__ fcw,   // [2]
    const float* __restrict__ fcb,   // [1]
    float* __restrict__ out)         // [B]
{
    const int b = blockIdx.x * 128 + threadIdx.x;

    // load this batch element's 9x6 gates (padded 56) as 14 aligned float4
    float v[GXPAD];
    {
        const float4* p = reinterpret_cast<const float4*>(&g_gx[(size_t)b * GXPAD]);
#pragma unroll
        for (int i = 0; i < GXPAD / 4; ++i)
            reinterpret_cast<float4*>(v)[i] = __ldg(p + i);
    }

    const float w00 = __ldg(Whh + 0),  w01 = __ldg(Whh + 1);
    const float w10 = __ldg(Whh + 2),  w11 = __ldg(Whh + 3);
    const float w20 = __ldg(Whh + 4),  w21 = __ldg(Whh + 5);
    const float w30 = __ldg(Whh + 6),  w31 = __ldg(Whh + 7);
    const float w40 = __ldg(Whh + 8),  w41 = __ldg(Whh + 9);
    const float w50 = __ldg(Whh + 10), w51 = __ldg(Whh + 11);
    const float bh0 = __ldg(bhh + 0), bh1 = __ldg(bhh + 1), bh2 = __ldg(bhh + 2);
    const float bh3 = __ldg(bhh + 3), bh4 = __ldg(bhh + 4), bh5 = __ldg(bhh + 5);

    float h0 = 0.0f, h1 = 0.0f;
#pragma unroll
    for (int t = 0; t < T_STEPS; ++t) {
        float q0 = v[6 * t + 0];
        float q1 = v[6 * t + 1];
        float q2 = v[6 * t + 2];
        float q3 = v[6 * t + 3];
        float q4 = v[6 * t + 4];
        float q5 = v[6 * t + 5];

        float a0 = w00 * h0 + w01 * h1 + bh0;
        float a1 = w10 * h0 + w11 * h1 + bh1;
        float a2 = w20 * h0 + w21 * h1 + bh2;
        float a3 = w30 * h0 + w31 * h1 + bh3;
        float a4 = w40 * h0 + w41 * h1 + bh4;
        float a5 = w50 * h0 + w51 * h1 + bh5;

        float r0 = sigf(q0 + a0);
        float r1 = sigf(q1 + a1);
        float z0 = sigf(q2 + a2);
        float z1 = sigf(q3 + a3);
        float n0 = tanh_ex(q4 + r0 * a4);
        float n1 = tanh_ex(q5 + r1 * a5);

        h0 = (1.0f - z0) * n0 + z0 * h0;
        h1 = (1.0f - z1) * n1 + z1 * h1;
    }

    out[b] = __ldg(fcw + 0) * h0 + __ldg(fcw + 1) * h1 + __ldg(fcb);
}

extern "C" void kernel_launch(void* const* d_in, const int* in_sizes, int n_in,
                              void* d_out, int out_size) {
    const float* x   = (const float*)d_in[0];
    const float* Wih = (const float*)d_in[1];
    const float* Whh = (const float*)d_in[2];
    const float* bih = (const float*)d_in[3];
    const float* bhh = (const float*)d_in[4];
    const float* fcw = (const float*)d_in[5];
    const float* fcb = (const float*)d_in[6];
    float* out = (float*)d_out;

    (void)in_sizes; (void)n_in; (void)out_size;

    gru_proj<<<K1_GRID, K1_THR>>>(x, Wih, bih);
    gru_recur<<<B_TOT / 128, 128>>>(Whh, bhh, fcw, fcb, out);
}

// round 9
// speedup vs baseline: 1.9290x; 1.2056x over previous
#include <cuda_runtime.h>
#include <cstdint>

// GRU_12962211299468 : B=65536, T=9, I=57, H=2, O=1, fp32
// Round 9: fix the MLP-vs-registers conflict in both kernels.
//  K1: tile staging via cp.async.cg (LDGSTS) -- no register footprint, all
//      15 x 512B per warp in flight; per-warp commit/wait + __syncwarp only.
//  K2: launch_bounds(128,1) so ptxas can hold all 14 staged float4 in regs
//      and front-batch the loads (round 8: regs=71 forced serialization).

#define T_STEPS 9
#define I_DIM   57
#define B_TOT   65536
#define NROWS_T (B_TOT * T_STEPS)       // 589824 rows
#define RPW     32                      // rows per warp
#define RPW_FLT (RPW * I_DIM)           // 1824 floats per warp tile
#define RPW_V4  (RPW_FLT / 4)           // 456 float4
#define WARPS_K1 (NROWS_T / RPW)        // 18432
#define CWARPS  4
#define K1_THR  (CWARPS * 32)           // 128
#define K1_GRID (WARPS_K1 / CWARPS)     // 4608
#define WROW    60
#define GXPAD   56

__device__ __align__(16) float g_gx[(size_t)B_TOT * GXPAD];   // 14.7 MB scratch

__device__ __forceinline__ uint32_t s2u(const void* p) {
    uint32_t a;
    asm("{ .reg .u64 t; cvta.to.shared.u64 t, %1; cvt.u32.u64 %0, t; }"
        : "=r"(a) : "l"(p));
    return a;
}
__device__ __forceinline__ void cp16(uint32_t dst, const float4* src) {
    asm volatile("cp.async.cg.shared.global [%0], [%1], 16;"
                 :: "r"(dst), "l"(src) : "memory");
}
__device__ __forceinline__ void cp_commit_wait0() {
    asm volatile("cp.async.commit_group;" ::: "memory");
    asm volatile("cp.async.wait_group 0;" ::: "memory");
}

__device__ __forceinline__ float sigf(float v) {
    return 1.0f / (1.0f + __expf(-v));
}
__device__ __forceinline__ float tanh_ex(float v) {
    return 1.0f - 2.0f / (__expf(2.0f * v) + 1.0f);
}

// ---------------------------------------------------------------- K1 ----
__global__ __launch_bounds__(K1_THR, 7) void gru_proj(
    const float* __restrict__ x,
    const float* __restrict__ Wih,   // [6,57]
    const float* __restrict__ bih)   // [6]
{
    __shared__ __align__(16) float sx[CWARPS][RPW_FLT];  // 4 x 7296 B
    __shared__ float sw[6 * WROW];                       // 1440 B

    const int tid  = threadIdx.x;
    const int wid  = tid >> 5;
    const int lane = tid & 31;

    for (int j = tid; j < 6 * WROW; j += K1_THR) {
        int g = j / WROW;
        int i = j - g * WROW;
        sw[j] = (i < I_DIM) ? Wih[g * I_DIM + i] : 0.0f;
    }
    __syncthreads();

    const float bi0 = bih[0], bi1 = bih[1], bi2 = bih[2];
    const float bi3 = bih[3], bi4 = bih[4], bi5 = bih[5];

    const int wg = blockIdx.x * CWARPS + wid;      // global warp id

    // ---- stage warp tile via cp.async: zero reg pressure, full MLP ----
    {
        const float4* src = reinterpret_cast<const float4*>(x) + (size_t)wg * RPW_V4;
        const uint32_t sb = s2u(&sx[wid][0]);
#pragma unroll
        for (int k = 0; k < 15; ++k) {
            int j = lane + 32 * k;
            if (j < RPW_V4) cp16(sb + 16u * (uint32_t)j, src + j);
        }
    }
    cp_commit_wait0();
    __syncwarp();

    // ---- lane = one row: 6 x 57 dot products ----
    const float* row = &sx[wid][lane * I_DIM];     // stride 57: conflict-free

    float g0 = bi0, g1 = bi1, g2 = bi2, g3 = bi3, g4 = bi4, g5 = bi5;
#pragma unroll
    for (int c = 0; c < 14; ++c) {
        float x0 = row[4 * c + 0];
        float x1 = row[4 * c + 1];
        float x2 = row[4 * c + 2];
        float x3 = row[4 * c + 3];
        float4 v;
        v = *reinterpret_cast<const float4*>(&sw[0 * WROW + 4 * c]);
        g0 += v.x * x0 + v.y * x1 + v.z * x2 + v.w * x3;
        v = *reinterpret_cast<const float4*>(&sw[1 * WROW + 4 * c]);
        g1 += v.x * x0 + v.y * x1 + v.z * x2 + v.w * x3;
        v = *reinterpret_cast<const float4*>(&sw[2 * WROW + 4 * c]);
        g2 += v.x * x0 + v.y * x1 + v.z * x2 + v.w * x3;
        v = *reinterpret_cast<const float4*>(&sw[3 * WROW + 4 * c]);
        g3 += v.x * x0 + v.y * x1 + v.z * x2 + v.w * x3;
        v = *reinterpret_cast<const float4*>(&sw[4 * WROW + 4 * c]);
        g4 += v.x * x0 + v.y * x1 + v.z * x2 + v.w * x3;
        v = *reinterpret_cast<const float4*>(&sw[5 * WROW + 4 * c]);
        g5 += v.x * x0 + v.y * x1 + v.z * x2 + v.w * x3;
    }
    {
        float xs = row[56];
        g0 += sw[0 * WROW + 56] * xs;
        g1 += sw[1 * WROW + 56] * xs;
        g2 += sw[2 * WROW + 56] * xs;
        g3 += sw[3 * WROW + 56] * xs;
        g4 += sw[4 * WROW + 56] * xs;
        g5 += sw[5 * WROW + 56] * xs;
    }

    const int r = wg * RPW + lane;                 // global row = 9b + t
    const int b = r / 9;
    const int t = r - 9 * b;
    float* o = &g_gx[(size_t)b * GXPAD + 6 * t];
    reinterpret_cast<float2*>(o)[0] = make_float2(g0, g1);
    reinterpret_cast<float2*>(o)[1] = make_float2(g2, g3);
    reinterpret_cast<float2*>(o)[2] = make_float2(g4, g5);
}

// ---------------------------------------------------------------- K2 ----
__global__ __launch_bounds__(128, 1) void gru_recur(
    const float* __restrict__ Whh,   // [6,2]
    const float* __restrict__ bhh,   // [6]
    const float* __restrict__ fcw,   // [2]
    const float* __restrict__ fcb,   // [1]
    float* __restrict__ out)         // [B]
{
    const int b = blockIdx.x * 128 + threadIdx.x;

    // all 14 float4 independent -> front-batched with the relaxed reg budget
    float v[GXPAD];
    {
        const float4* p = reinterpret_cast<const float4*>(&g_gx[(size_t)b * GXPAD]);
#pragma unroll
        for (int i = 0; i < GXPAD / 4; ++i)
            reinterpret_cast<float4*>(v)[i] = __ldg(p + i);
    }

    const float w00 = __ldg(Whh + 0),  w01 = __ldg(Whh + 1);
    const float w10 = __ldg(Whh + 2),  w11 = __ldg(Whh + 3);
    const float w20 = __ldg(Whh + 4),  w21 = __ldg(Whh + 5);
    const float w30 = __ldg(Whh + 6),  w31 = __ldg(Whh + 7);
    const float w40 = __ldg(Whh + 8),  w41 = __ldg(Whh + 9);
    const float w50 = __ldg(Whh + 10), w51 = __ldg(Whh + 11);
    const float bh0 = __ldg(bhh + 0), bh1 = __ldg(bhh + 1), bh2 = __ldg(bhh + 2);
    const float bh3 = __ldg(bhh + 3), bh4 = __ldg(bhh + 4), bh5 = __ldg(bhh + 5);

    float h0 = 0.0f, h1 = 0.0f;
#pragma unroll
    for (int t = 0; t < T_STEPS; ++t) {
        float q0 = v[6 * t + 0];
        float q1 = v[6 * t + 1];
        float q2 = v[6 * t + 2];
        float q3 = v[6 * t + 3];
        float q4 = v[6 * t + 4];
        float q5 = v[6 * t + 5];

        float a0 = w00 * h0 + w01 * h1 + bh0;
        float a1 = w10 * h0 + w11 * h1 + bh1;
        float a2 = w20 * h0 + w21 * h1 + bh2;
        float a3 = w30 * h0 + w31 * h1 + bh3;
        float a4 = w40 * h0 + w41 * h1 + bh4;
        float a5 = w50 * h0 + w51 * h1 + bh5;

        float r0 = sigf(q0 + a0);
        float r1 = sigf(q1 + a1);
        float z0 = sigf(q2 + a2);
        float z1 = sigf(q3 + a3);
        float n0 = tanh_ex(q4 + r0 * a4);
        float n1 = tanh_ex(q5 + r1 * a5);

        h0 = (1.0f - z0) * n0 + z0 * h0;
        h1 = (1.0f - z1) * n1 + z1 * h1;
    }

    out[b] = __ldg(fcw + 0) * h0 + __ldg(fcw + 1) * h1 + __ldg(fcb);
}

extern "C" void kernel_launch(void* const* d_in, const int* in_sizes, int n_in,
                              void* d_out, int out_size) {
    const float* x   = (const float*)d_in[0];
    const float* Wih = (const float*)d_in[1];
    const float* Whh = (const float*)d_in[2];
    const float* bih = (const float*)d_in[3];
    const float* bhh = (const float*)d_in[4];
    const float* fcw = (const float*)d_in[5];
    const float* fcb = (const float*)d_in[6];
    float* out = (float*)d_out;

    (void)in_sizes; (void)n_in; (void)out_size;

    gru_proj<<<K1_GRID, K1_THR>>>(x, Wih, bih);
    gru_recur<<<B_TOT / 128, 128>>>(Whh, bhh, fcw, fcb, out);
}

// round 10
// speedup vs baseline: 1.9431x; 1.0073x over previous
#include <cuda_runtime.h>
#include <cstdint>

// GRU_12962211299468 : B=65536, T=9, I=57, H=2, O=1, fp32
// Round 10: transpose the gx scratch to [54][B] (s = 6t+g major, batch minor).
//   K2's per-thread reads become per-warp coalesced (784 -> 54 L1 wavefronts
//   per warp, the round-9 limiter); K1's stores drop 168 -> ~60 wf/warp.
//  K1: warp-private tiles via cp.async (unchanged, proven 27.7us).
//  K2: thread = batch element, 54 coalesced LDG.32, register recurrence.

#define T_STEPS 9
#define I_DIM   57
#define B_TOT   65536
#define NROWS_T (B_TOT * T_STEPS)       // 589824 rows
#define RPW     32                      // rows per warp
#define RPW_FLT (RPW * I_DIM)           // 1824 floats per warp tile
#define RPW_V4  (RPW_FLT / 4)           // 456 float4
#define WARPS_K1 (NROWS_T / RPW)        // 18432
#define CWARPS  4
#define K1_THR  (CWARPS * 32)           // 128
#define K1_GRID (WARPS_K1 / CWARPS)     // 4608
#define WROW    60
#define NGATES  (T_STEPS * 6)           // 54

__device__ float g_gx[NGATES * B_TOT];  // transposed scratch: [s][b], 14.2 MB

__device__ __forceinline__ uint32_t s2u(const void* p) {
    uint32_t a;
    asm("{ .reg .u64 t; cvta.to.shared.u64 t, %1; cvt.u32.u64 %0, t; }"
        : "=r"(a) : "l"(p));
    return a;
}
__device__ __forceinline__ void cp16(uint32_t dst, const float4* src) {
    asm volatile("cp.async.cg.shared.global [%0], [%1], 16;"
                 :: "r"(dst), "l"(src) : "memory");
}
__device__ __forceinline__ void cp_commit_wait0() {
    asm volatile("cp.async.commit_group;" ::: "memory");
    asm volatile("cp.async.wait_group 0;" ::: "memory");
}

__device__ __forceinline__ float sigf(float v) {
    return 1.0f / (1.0f + __expf(-v));
}
__device__ __forceinline__ float tanh_ex(float v) {
    return 1.0f - 2.0f / (__expf(2.0f * v) + 1.0f);
}

// ---------------------------------------------------------------- K1 ----
__global__ __launch_bounds__(K1_THR, 7) void gru_proj(
    const float* __restrict__ x,
    const float* __restrict__ Wih,   // [6,57]
    const float* __restrict__ bih)   // [6]
{
    __shared__ __align__(16) float sx[CWARPS][RPW_FLT];  // 4 x 7296 B
    __shared__ float sw[6 * WROW];                       // 1440 B

    const int tid  = threadIdx.x;
    const int wid  = tid >> 5;
    const int lane = tid & 31;

    for (int j = tid; j < 6 * WROW; j += K1_THR) {
        int g = j / WROW;
        int i = j - g * WROW;
        sw[j] = (i < I_DIM) ? Wih[g * I_DIM + i] : 0.0f;
    }
    __syncthreads();

    const float bi0 = bih[0], bi1 = bih[1], bi2 = bih[2];
    const float bi3 = bih[3], bi4 = bih[4], bi5 = bih[5];

    const int wg = blockIdx.x * CWARPS + wid;      // global warp id

    // ---- stage warp tile via cp.async: zero reg pressure, full MLP ----
    {
        const float4* src = reinterpret_cast<const float4*>(x) + (size_t)wg * RPW_V4;
        const uint32_t sb = s2u(&sx[wid][0]);
#pragma unroll
        for (int k = 0; k < 15; ++k) {
            int j = lane + 32 * k;
            if (j < RPW_V4) cp16(sb + 16u * (uint32_t)j, src + j);
        }
    }
    cp_commit_wait0();
    __syncwarp();

    // ---- lane = one row: 6 x 57 dot products ----
    const float* row = &sx[wid][lane * I_DIM];     // stride 57: conflict-free

    float g0 = bi0, g1 = bi1, g2 = bi2, g3 = bi3, g4 = bi4, g5 = bi5;
#pragma unroll
    for (int c = 0; c < 14; ++c) {
        float x0 = row[4 * c + 0];
        float x1 = row[4 * c + 1];
        float x2 = row[4 * c + 2];
        float x3 = row[4 * c + 3];
        float4 v;
        v = *reinterpret_cast<const float4*>(&sw[0 * WROW + 4 * c]);
        g0 += v.x * x0 + v.y * x1 + v.z * x2 + v.w * x3;
        v = *reinterpret_cast<const float4*>(&sw[1 * WROW + 4 * c]);
        g1 += v.x * x0 + v.y * x1 + v.z * x2 + v.w * x3;
        v = *reinterpret_cast<const float4*>(&sw[2 * WROW + 4 * c]);
        g2 += v.x * x0 + v.y * x1 + v.z * x2 + v.w * x3;
        v = *reinterpret_cast<const float4*>(&sw[3 * WROW + 4 * c]);
        g3 += v.x * x0 + v.y * x1 + v.z * x2 + v.w * x3;
        v = *reinterpret_cast<const float4*>(&sw[4 * WROW + 4 * c]);
        g4 += v.x * x0 + v.y * x1 + v.z * x2 + v.w * x3;
        v = *reinterpret_cast<const float4*>(&sw[5 * WROW + 4 * c]);
        g5 += v.x * x0 + v.y * x1 + v.z * x2 + v.w * x3;
    }
    {
        float xs = row[56];
        g0 += sw[0 * WROW + 56] * xs;
        g1 += sw[1 * WROW + 56] * xs;
        g2 += sw[2 * WROW + 56] * xs;
        g3 += sw[3 * WROW + 56] * xs;
        g4 += sw[4 * WROW + 56] * xs;
        g5 += sw[5 * WROW + 56] * xs;
    }

    // ---- scatter to transposed gx: s-major, batch-minor ----
    const int r = wg * RPW + lane;                 // global row = 9b + t
    const int b = r / 9;
    const int t = r - 9 * b;
    float* o = &g_gx[(size_t)(6 * t) * B_TOT + b];
    o[0 * B_TOT] = g0;
    o[1 * B_TOT] = g1;
    o[2 * B_TOT] = g2;
    o[3 * B_TOT] = g3;
    o[4 * B_TOT] = g4;
    o[5 * B_TOT] = g5;
}

// ---------------------------------------------------------------- K2 ----
__global__ __launch_bounds__(128, 1) void gru_recur(
    const float* __restrict__ Whh,   // [6,2]
    const float* __restrict__ bhh,   // [6]
    const float* __restrict__ fcw,   // [2]
    const float* __restrict__ fcb,   // [1]
    float* __restrict__ out)         // [B]
{
    const int b = blockIdx.x * 128 + threadIdx.x;

    // 54 fully coalesced, independent LDG.32 (lanes read consecutive b)
    float v[NGATES];
#pragma unroll
    for (int s = 0; s < NGATES; ++s)
        v[s] = __ldg(&g_gx[(size_t)s * B_TOT + b]);

    const float w00 = __ldg(Whh + 0),  w01 = __ldg(Whh + 1);
    const float w10 = __ldg(Whh + 2),  w11 = __ldg(Whh + 3);
    const float w20 = __ldg(Whh + 4),  w21 = __ldg(Whh + 5);
    const float w30 = __ldg(Whh + 6),  w31 = __ldg(Whh + 7);
    const float w40 = __ldg(Whh + 8),  w41 = __ldg(Whh + 9);
    const float w50 = __ldg(Whh + 10), w51 = __ldg(Whh + 11);
    const float bh0 = __ldg(bhh + 0), bh1 = __ldg(bhh + 1), bh2 = __ldg(bhh + 2);
    const float bh3 = __ldg(bhh + 3), bh4 = __ldg(bhh + 4), bh5 = __ldg(bhh + 5);

    float h0 = 0.0f, h1 = 0.0f;
#pragma unroll
    for (int t = 0; t < T_STEPS; ++t) {
        float q0 = v[6 * t + 0];
        float q1 = v[6 * t + 1];
        float q2 = v[6 * t + 2];
        float q3 = v[6 * t + 3];
        float q4 = v[6 * t + 4];
        float q5 = v[6 * t + 5];

        float a0 = w00 * h0 + w01 * h1 + bh0;
        float a1 = w10 * h0 + w11 * h1 + bh1;
        float a2 = w20 * h0 + w21 * h1 + bh2;
        float a3 = w30 * h0 + w31 * h1 + bh3;
        float a4 = w40 * h0 + w41 * h1 + bh4;
        float a5 = w50 * h0 + w51 * h1 + bh5;

        float r0 = sigf(q0 + a0);
        float r1 = sigf(q1 + a1);
        float z0 = sigf(q2 + a2);
        float z1 = sigf(q3 + a3);
        float n0 = tanh_ex(q4 + r0 * a4);
        float n1 = tanh_ex(q5 + r1 * a5);

        h0 = (1.0f - z0) * n0 + z0 * h0;
        h1 = (1.0f - z1) * n1 + z1 * h1;
    }

    out[b] = __ldg(fcw + 0) * h0 + __ldg(fcw + 1) * h1 + __ldg(fcb);
}

extern "C" void kernel_launch(void* const* d_in, const int* in_sizes, int n_in,
                              void* d_out, int out_size) {
    const float* x   = (const float*)d_in[0];
    const float* Wih = (const float*)d_in[1];
    const float* Whh = (const float*)d_in[2];
    const float* bih = (const float*)d_in[3];
    const float* bhh = (const float*)d_in[4];
    const float* fcw = (const float*)d_in[5];
    const float* fcb = (const float*)d_in[6];
    float* out = (float*)d_out;

    (void)in_sizes; (void)n_in; (void)out_size;

    gru_proj<<<K1_GRID, K1_THR>>>(x, Wih, bih);
    gru_recur<<<B_TOT / 128, 128>>>(Whh, bhh, fcw, fcb, out);
}